// round 3
// baseline (speedup 1.0000x reference)
#include <cuda_runtime.h>
#include <math.h>
#include <stdint.h>

#define Bc    8
#define Hc    128
#define Wc    128
#define Dc    256
#define Nc    8192
#define MLPW  256
#define INDIM 813          // 2 + 40 + 768 + 3
#define TILE  32
#define SMEM_BYTES (INDIM * TILE * 4)

// ---------------- device scratch (static, allowed) ----------------
__device__ float g_t1[Bc * Hc * 64 * Dc];   // W-pass 128->64   (67 MB)
__device__ float g_l1[Bc * 64 * 64 * Dc];   // level1           (33 MB)
__device__ float g_t2[Bc * Hc * 32 * Dc];   // W-pass 128->32   (33 MB)
__device__ float g_l2[Bc * 32 * 32 * Dc];   // level2           (8 MB)
__device__ float g_film[Bc * 2 * MLPW];     // ctx @ ctx_w + ctx_b

// ---------------- f32x2 packed-FMA helpers ----------------
__device__ __forceinline__ uint64_t pack2(float x) {
    uint64_t r;
    asm("mov.b64 %0, {%1, %1};" : "=l"(r) : "f"(x));
    return r;
}
__device__ __forceinline__ void ffma2(uint64_t& d, uint64_t a, uint64_t b) {
    asm("fma.rn.f32x2 %0, %1, %2, %0;" : "+l"(d) : "l"(a), "l"(b));
}
__device__ __forceinline__ float2 unpack2(uint64_t v) {
    float2 r;
    asm("mov.b64 {%0, %1}, %2;" : "=f"(r.x), "=f"(r.y) : "l"(v));
    return r;
}

// ---------------- separable antialiased triangle resize ----------------
template <int INV, int HL, int WIN>
__device__ __forceinline__ void resize_w_body(const float* __restrict__ in,
                                              float* __restrict__ out) {
    const int WOUT = WIN / INV;
    const int NT = 2 * INV;
    int idx = blockIdx.x * blockDim.x + threadIdx.x;
    if (idx >= Bc * HL * WOUT * (Dc / 4)) return;
    int d4 = idx & 63;
    int t = idx >> 6;
    int xo = t % WOUT; t /= WOUT;
    int y = t % HL;
    int b = t / HL;

    float sf = (xo + 0.5f) * INV - 0.5f;
    int j0 = INV * xo - (INV / 2);
    float w[NT];
    float wsum = 0.f;
#pragma unroll
    for (int i = 0; i < NT; i++) {
        int j = j0 + i;
        float ww = 1.0f - fabsf((float)j - sf) * (1.0f / INV);
        ww = (j >= 0 && j < WIN) ? fmaxf(ww, 0.f) : 0.f;
        w[i] = ww;
        wsum += ww;
    }
    float inv = 1.0f / wsum;
    const float4* ip = (const float4*)in + ((size_t)(b * HL + y) * WIN) * 64 + d4;
    float4 acc = make_float4(0.f, 0.f, 0.f, 0.f);
#pragma unroll
    for (int i = 0; i < NT; i++) {
        if (w[i] > 0.f) {
            float4 v = __ldg(&ip[(j0 + i) * 64]);
            float ww = w[i] * inv;
            acc.x += ww * v.x; acc.y += ww * v.y;
            acc.z += ww * v.z; acc.w += ww * v.w;
        }
    }
    ((float4*)out)[((size_t)(b * HL + y) * WOUT + xo) * 64 + d4] = acc;
}

template <int INV, int HIN, int WL>
__device__ __forceinline__ void resize_h_body(const float* __restrict__ in,
                                              float* __restrict__ out) {
    const int HOUT = HIN / INV;
    const int NT = 2 * INV;
    int idx = blockIdx.x * blockDim.x + threadIdx.x;
    if (idx >= Bc * HOUT * WL * (Dc / 4)) return;
    int d4 = idx & 63;
    int t = idx >> 6;
    int x = t % WL; t /= WL;
    int yo = t % HOUT;
    int b = t / HOUT;

    float sf = (yo + 0.5f) * INV - 0.5f;
    int j0 = INV * yo - (INV / 2);
    float w[NT];
    float wsum = 0.f;
#pragma unroll
    for (int i = 0; i < NT; i++) {
        int j = j0 + i;
        float ww = 1.0f - fabsf((float)j - sf) * (1.0f / INV);
        ww = (j >= 0 && j < HIN) ? fmaxf(ww, 0.f) : 0.f;
        w[i] = ww;
        wsum += ww;
    }
    float inv = 1.0f / wsum;
    const float4* ip = (const float4*)in + ((size_t)b * HIN * WL + x) * 64 + d4;
    float4 acc = make_float4(0.f, 0.f, 0.f, 0.f);
#pragma unroll
    for (int i = 0; i < NT; i++) {
        if (w[i] > 0.f) {
            float4 v = __ldg(&ip[(size_t)(j0 + i) * WL * 64]);
            float ww = w[i] * inv;
            acc.x += ww * v.x; acc.y += ww * v.y;
            acc.z += ww * v.z; acc.w += ww * v.w;
        }
    }
    ((float4*)out)[((size_t)(b * HOUT + yo) * WL + x) * 64 + d4] = acc;
}

__global__ void resize_w2_kernel(const float* __restrict__ in) { resize_w_body<2, Hc, Wc>(in, g_t1); }
__global__ void resize_h2_kernel() { resize_h_body<2, Hc, 64>(g_t1, g_l1); }
__global__ void resize_w4_kernel(const float* __restrict__ in) { resize_w_body<4, Hc, Wc>(in, g_t2); }
__global__ void resize_h4_kernel() { resize_h_body<4, Hc, 32>(g_t2, g_l2); }

// ---------------- FiLM: ctx = context_vector @ ctx_w + ctx_b ----------------
__global__ void film_kernel(const float* __restrict__ cv,
                            const float* __restrict__ cw,
                            const float* __restrict__ cb) {
    int b = blockIdx.x;
    int j = threadIdx.x;             // 512 threads
    float acc = cb[j];
    for (int k = 0; k < Dc; k++)
        acc = fmaf(cv[b * Dc + k], cw[k * 512 + j], acc);
    g_film[b * 512 + j] = acc;
}

// ---------------- fused gather + MLP ----------------
__device__ __forceinline__ float gelu_t(float x) {
    float x3 = x * x * x;
    float t = tanhf(0.7978845608028654f * (x + 0.044715f * x3));
    return 0.5f * x * (1.0f + t);
}

// GEMM: thread owns columns (c0, c0+1) and samples [s0, s0+16).
// Per k: 1 LDG.64 (2 weights), 4 LDS.128 (16 samples as 8 u64), 16 FFMA2.
__device__ __forceinline__ void gemm2(const float* __restrict__ hbuf,
                                      const float* __restrict__ w,
                                      int K, int c0, int s0,
                                      uint64_t acc[2][8]) {
#pragma unroll
    for (int c = 0; c < 2; c++)
#pragma unroll
        for (int j = 0; j < 8; j++) acc[c][j] = 0ull;
    const float* hb = hbuf + s0;
#pragma unroll 4
    for (int k = 0; k < K; k++) {
        float2 wv = *(const float2*)(w + (size_t)k * MLPW + c0);
        uint64_t w0p = pack2(wv.x);
        uint64_t w1p = pack2(wv.y);
        const ulonglong2* hr = (const ulonglong2*)(hb + k * TILE);
#pragma unroll
        for (int j = 0; j < 4; j++) {
            ulonglong2 hv = hr[j];
            ffma2(acc[0][2 * j + 0], w0p, hv.x);
            ffma2(acc[0][2 * j + 1], w0p, hv.y);
            ffma2(acc[1][2 * j + 0], w1p, hv.x);
            ffma2(acc[1][2 * j + 1], w1p, hv.y);
        }
    }
}

// gelu((acc + bias) * gamma + beta) then store back to hbuf[col][sample].
__device__ __forceinline__ void act_store(uint64_t acc[2][8],
                                          float bias0, float bias1,
                                          float2 gm, float2 bt,
                                          float* hbuf, int c0, int s0) {
    float v[2][16];
#pragma unroll
    for (int c = 0; c < 2; c++) {
        float bias = c ? bias1 : bias0;
        float g = c ? gm.y : gm.x;
        float be = c ? bt.y : bt.x;
#pragma unroll
        for (int j = 0; j < 8; j++) {
            float2 p = unpack2(acc[c][j]);
            v[c][2 * j + 0] = gelu_t((p.x + bias) * g + be);
            v[c][2 * j + 1] = gelu_t((p.y + bias) * g + be);
        }
    }
    __syncthreads();
#pragma unroll
    for (int c = 0; c < 2; c++) {
        float4* dst = (float4*)(hbuf + (c0 + c) * TILE + s0);
#pragma unroll
        for (int j = 0; j < 4; j++)
            dst[j] = make_float4(v[c][4 * j + 0], v[c][4 * j + 1],
                                 v[c][4 * j + 2], v[c][4 * j + 3]);
    }
    __syncthreads();
}

__global__ void __launch_bounds__(256)
fused_kernel(const float* __restrict__ grid,
             const float* __restrict__ coords,
             const float* __restrict__ oracle,
             const float* __restrict__ w0, const float* __restrict__ b0,
             const float* __restrict__ hw, const float* __restrict__ hb,
             const float* __restrict__ ow, const float* __restrict__ ob,
             float* __restrict__ out) {
    extern __shared__ float hbuf[];          // [INDIM][TILE]
    __shared__ int   s_off[3][TILE][4];      // float4-unit offsets
    __shared__ float s_w[3][TILE][4];

    int tid = threadIdx.x;
    int blk = blockIdx.x;
    int b = blk >> 8;                        // 256 tiles per batch
    int n0 = (blk & 255) * TILE;

    // ---- positional encoding + oracle ----
    if (tid < TILE) {
        int r = tid;
        int n = n0 + r;
        float c0 = coords[2 * n], c1 = coords[2 * n + 1];
        hbuf[0 * TILE + r] = c0;
        hbuf[1 * TILE + r] = c1;
        float pf = 3.14159265358979323846f;
#pragma unroll
        for (int f = 0; f < 10; f++) {
            float s0, q0, s1, q1;
            sincosf(c0 * pf, &s0, &q0);
            sincosf(c1 * pf, &s1, &q1);
            hbuf[(2 + 4 * f + 0) * TILE + r] = s0;
            hbuf[(2 + 4 * f + 1) * TILE + r] = s1;
            hbuf[(2 + 4 * f + 2) * TILE + r] = q0;
            hbuf[(2 + 4 * f + 3) * TILE + r] = q1;
            pf *= 2.0f;
        }
#pragma unroll
        for (int j = 0; j < 3; j++)
            hbuf[(810 + j) * TILE + r] = oracle[((size_t)b * Nc + n) * 3 + j];
    }

    // ---- bilinear-sample metadata (3 levels x 32 samples) ----
    if (tid < 96) {
        int lvl = tid >> 5;
        int r = tid & 31;
        int n = n0 + r;
        int Hl = Hc >> lvl, Wl = Wc >> lvl;
        float c0 = coords[2 * n], c1 = coords[2 * n + 1];
        float y = (c0 + 1.0f) * 0.5f * (Hl - 1);
        float x = (c1 + 1.0f) * 0.5f * (Wl - 1);
        float y0f = fminf(fmaxf(floorf(y), 0.f), (float)(Hl - 1));
        float x0f = fminf(fmaxf(floorf(x), 0.f), (float)(Wl - 1));
        int y0 = (int)y0f, x0 = (int)x0f;
        int y1 = min(y0 + 1, Hl - 1), x1 = min(x0 + 1, Wl - 1);
        float wy = y - y0f, wx = x - x0f;
        int base = b * Hl * Wl;
        s_off[lvl][r][0] = (base + y0 * Wl + x0) * 64;
        s_off[lvl][r][1] = (base + y0 * Wl + x1) * 64;
        s_off[lvl][r][2] = (base + y1 * Wl + x0) * 64;
        s_off[lvl][r][3] = (base + y1 * Wl + x1) * 64;
        s_w[lvl][r][0] = (1.f - wy) * (1.f - wx);
        s_w[lvl][r][1] = (1.f - wy) * wx;
        s_w[lvl][r][2] = wy * (1.f - wx);
        s_w[lvl][r][3] = wy * wx;
    }
    __syncthreads();

    // ---- gather 3x256 feature channels ----
    {
        int r = tid & 31;
        int jl = tid >> 5;   // 0..7
        const float* srcs[3] = {grid, g_l1, g_l2};
#pragma unroll
        for (int lvl = 0; lvl < 3; lvl++) {
            const float4* src = (const float4*)srcs[lvl];
            int o0 = s_off[lvl][r][0], o1 = s_off[lvl][r][1];
            int o2 = s_off[lvl][r][2], o3 = s_off[lvl][r][3];
            float w0v = s_w[lvl][r][0], w1v = s_w[lvl][r][1];
            float w2v = s_w[lvl][r][2], w3v = s_w[lvl][r][3];
#pragma unroll
            for (int ch = 0; ch < 8; ch++) {
                int d4 = jl + 8 * ch;
                float4 a = __ldg(&src[o0 + d4]);
                float4 bb = __ldg(&src[o1 + d4]);
                float4 c = __ldg(&src[o2 + d4]);
                float4 d = __ldg(&src[o3 + d4]);
                int k = 42 + lvl * 256 + d4 * 4;
                hbuf[(k + 0) * TILE + r] = w0v * a.x + w1v * bb.x + w2v * c.x + w3v * d.x;
                hbuf[(k + 1) * TILE + r] = w0v * a.y + w1v * bb.y + w2v * c.y + w3v * d.y;
                hbuf[(k + 2) * TILE + r] = w0v * a.z + w1v * bb.z + w2v * c.z + w3v * d.z;
                hbuf[(k + 3) * TILE + r] = w0v * a.w + w1v * bb.w + w2v * c.w + w3v * d.w;
            }
        }
    }
    __syncthreads();

    int c0 = (tid & 127) * 2;     // column pair
    int s0 = (tid >> 7) * 16;     // sample half

    float2 gm = make_float2(g_film[b * 512 + c0] + 1.0f,
                            g_film[b * 512 + c0 + 1] + 1.0f);
    float2 bt = make_float2(g_film[b * 512 + 256 + c0],
                            g_film[b * 512 + 256 + c0 + 1]);

    uint64_t acc[2][8];

    // ---- layer 0: 813 -> 256 ----
    gemm2(hbuf, w0, INDIM, c0, s0, acc);
    act_store(acc, b0[c0], b0[c0 + 1], gm, bt, hbuf, c0, s0);

    // ---- hidden layers: 3 x (256 -> 256) ----
#pragma unroll
    for (int L = 0; L < 3; L++) {
        gemm2(hbuf, hw + (size_t)L * MLPW * MLPW, MLPW, c0, s0, acc);
        act_store(acc, hb[L * MLPW + c0], hb[L * MLPW + c0 + 1], gm, bt,
                  hbuf, c0, s0);
    }

    // ---- output layer: 256 -> 3, tanh ----
    if (tid < 96) {
        int o = tid >> 5;    // 0..2
        int r = tid & 31;
        float a = ob[o];
        for (int k = 0; k < MLPW; k++)
            a = fmaf(hbuf[k * TILE + r], __ldg(ow + k * 3 + o), a);
        out[((size_t)b * Nc + n0 + r) * 3 + o] = tanhf(a);
    }
}

// ---------------- launch ----------------
extern "C" void kernel_launch(void* const* d_in, const int* in_sizes, int n_in,
                              void* d_out, int out_size) {
    const float* grid   = (const float*)d_in[0];
    const float* cv     = (const float*)d_in[1];
    const float* coords = (const float*)d_in[2];
    const float* oracle = (const float*)d_in[3];
    const float* w0     = (const float*)d_in[4];
    const float* b0     = (const float*)d_in[5];
    const float* hw     = (const float*)d_in[6];
    const float* hb     = (const float*)d_in[7];
    const float* cw     = (const float*)d_in[8];
    const float* cb     = (const float*)d_in[9];
    const float* ow     = (const float*)d_in[10];
    const float* ob     = (const float*)d_in[11];
    float* out = (float*)d_out;

    cudaFuncSetAttribute(fused_kernel, cudaFuncAttributeMaxDynamicSharedMemorySize, SMEM_BYTES);

    resize_w2_kernel<<<(Bc * Hc * 64 * 64 + 255) / 256, 256>>>(grid);
    resize_h2_kernel<<<(Bc * 64 * 64 * 64 + 255) / 256, 256>>>();
    resize_w4_kernel<<<(Bc * Hc * 32 * 64 + 255) / 256, 256>>>(grid);
    resize_h4_kernel<<<(Bc * 32 * 32 * 64 + 255) / 256, 256>>>();
    film_kernel<<<Bc, 512>>>(cv, cw, cb);
    fused_kernel<<<Bc * Nc / TILE, 256, SMEM_BYTES>>>(grid, coords, oracle,
                                                      w0, b0, hw, hb, ow, ob, out);
}

// round 6
// speedup vs baseline: 1.5433x; 1.5433x over previous
#include <cuda_runtime.h>
#include <cuda_bf16.h>
#include <math.h>
#include <stdint.h>

#define Bc    8
#define Hc    128
#define Wc    128
#define Dc    256
#define Nc    8192
#define KPAD0 832
#define THREADS 256

// SMEM byte offsets
#define KS       264            // bf16 stride per activation row (528B = 33*16B)
#define A_HI     0              // 64*264*2 = 33792
#define A_LO     33792
#define SM_METAO 67584          // 3*64*4 int
#define SM_METAW 70656          // 3*64*4 float
#define SM_GAMMA 73728          // 256 f32
#define SM_BETA  74752
#define SM_BIAS  75776          // 4*256 f32
#define SM_OW    79872          // 771 f32
#define SM_PSUM  82960          // 64*3 f32
#define SM_TOTAL 83776

// ---------------- device scratch ----------------
__device__ float g_t1[Bc * Hc * 64 * Dc];
__device__ float g_l1[Bc * 64 * 64 * Dc];
__device__ float g_t2[Bc * Hc * 32 * Dc];
__device__ float g_l2[Bc * 32 * 32 * Dc];
__device__ float g_film[Bc * 512];
__device__ __align__(16) __nv_bfloat16 g_w0t_hi[256 * KPAD0];
__device__ __align__(16) __nv_bfloat16 g_w0t_lo[256 * KPAD0];
__device__ __align__(16) __nv_bfloat16 g_hwt_hi[3 * 256 * 256];
__device__ __align__(16) __nv_bfloat16 g_hwt_lo[3 * 256 * 256];

// ---------------- helpers ----------------
__device__ __forceinline__ uint32_t smem_u32(const void* p) {
    uint32_t a;
    asm("{ .reg .u64 t; cvta.to.shared.u64 t, %1; cvt.u32.u64 %0, t; }" : "=r"(a) : "l"(p));
    return a;
}
__device__ __forceinline__ void ldm4(uint32_t* r, uint32_t addr) {
    asm volatile("ldmatrix.sync.aligned.m8n8.x4.shared.b16 {%0,%1,%2,%3}, [%4];"
        : "=r"(r[0]), "=r"(r[1]), "=r"(r[2]), "=r"(r[3]) : "r"(addr));
}
__device__ __forceinline__ void mma16816(float* c, const uint32_t* a, uint32_t b0, uint32_t b1) {
    asm volatile("mma.sync.aligned.m16n8k16.row.col.f32.bf16.bf16.f32 "
        "{%0,%1,%2,%3}, {%4,%5,%6,%7}, {%8,%9}, {%0,%1,%2,%3};"
        : "+f"(c[0]), "+f"(c[1]), "+f"(c[2]), "+f"(c[3])
        : "r"(a[0]), "r"(a[1]), "r"(a[2]), "r"(a[3]), "r"(b0), "r"(b1));
}
__device__ __forceinline__ uint32_t pack_hi(float x, float y) {
    __nv_bfloat162 v(__float2bfloat16(x), __float2bfloat16(y));
    return *(uint32_t*)&v;
}
__device__ __forceinline__ uint32_t pack_lo(float x, float y) {
    float hx = __bfloat162float(__float2bfloat16(x));
    float hy = __bfloat162float(__float2bfloat16(y));
    __nv_bfloat162 v(__float2bfloat16(x - hx), __float2bfloat16(y - hy));
    return *(uint32_t*)&v;
}
__device__ __forceinline__ float gelu_t(float x) {
    float x3 = x * x * x;
    float t = tanhf(0.7978845608028654f * (x + 0.044715f * x3));
    return 0.5f * x * (1.0f + t);
}

// ---------------- resize (antialiased triangle, separable) ----------------
template <int INV, int HL, int WIN>
__device__ __forceinline__ void resize_w_body(const float* __restrict__ in, float* __restrict__ out) {
    const int WOUT = WIN / INV, NT = 2 * INV;
    int idx = blockIdx.x * blockDim.x + threadIdx.x;
    if (idx >= Bc * HL * WOUT * 64) return;
    int d4 = idx & 63, t = idx >> 6;
    int xo = t % WOUT; t /= WOUT;
    int y = t % HL, b = t / HL;
    float sf = (xo + 0.5f) * INV - 0.5f;
    int j0 = INV * xo - (INV / 2);
    float w[NT], wsum = 0.f;
#pragma unroll
    for (int i = 0; i < NT; i++) {
        int j = j0 + i;
        float ww = 1.0f - fabsf((float)j - sf) * (1.0f / INV);
        ww = (j >= 0 && j < WIN) ? fmaxf(ww, 0.f) : 0.f;
        w[i] = ww; wsum += ww;
    }
    float inv = 1.0f / wsum;
    const float4* ip = (const float4*)in + ((size_t)(b * HL + y) * WIN) * 64 + d4;
    float4 acc = make_float4(0.f, 0.f, 0.f, 0.f);
#pragma unroll
    for (int i = 0; i < NT; i++)
        if (w[i] > 0.f) {
            float4 v = __ldg(&ip[(j0 + i) * 64]);
            float ww = w[i] * inv;
            acc.x += ww * v.x; acc.y += ww * v.y; acc.z += ww * v.z; acc.w += ww * v.w;
        }
    ((float4*)out)[((size_t)(b * HL + y) * WOUT + xo) * 64 + d4] = acc;
}
template <int INV, int HIN, int WL>
__device__ __forceinline__ void resize_h_body(const float* __restrict__ in, float* __restrict__ out) {
    const int HOUT = HIN / INV, NT = 2 * INV;
    int idx = blockIdx.x * blockDim.x + threadIdx.x;
    if (idx >= Bc * HOUT * WL * 64) return;
    int d4 = idx & 63, t = idx >> 6;
    int x = t % WL; t /= WL;
    int yo = t % HOUT, b = t / HOUT;
    float sf = (yo + 0.5f) * INV - 0.5f;
    int j0 = INV * yo - (INV / 2);
    float w[NT], wsum = 0.f;
#pragma unroll
    for (int i = 0; i < NT; i++) {
        int j = j0 + i;
        float ww = 1.0f - fabsf((float)j - sf) * (1.0f / INV);
        ww = (j >= 0 && j < HIN) ? fmaxf(ww, 0.f) : 0.f;
        w[i] = ww; wsum += ww;
    }
    float inv = 1.0f / wsum;
    const float4* ip = (const float4*)in + ((size_t)b * HIN * WL + x) * 64 + d4;
    float4 acc = make_float4(0.f, 0.f, 0.f, 0.f);
#pragma unroll
    for (int i = 0; i < NT; i++)
        if (w[i] > 0.f) {
            float4 v = __ldg(&ip[(size_t)(j0 + i) * WL * 64]);
            float ww = w[i] * inv;
            acc.x += ww * v.x; acc.y += ww * v.y; acc.z += ww * v.z; acc.w += ww * v.w;
        }
    ((float4*)out)[((size_t)(b * HOUT + yo) * WL + x) * 64 + d4] = acc;
}
__global__ void resize_w2_kernel(const float* __restrict__ in) { resize_w_body<2, Hc, Wc>(in, g_t1); }
__global__ void resize_h2_kernel() { resize_h_body<2, Hc, 64>(g_t1, g_l1); }
__global__ void resize_w4_kernel(const float* __restrict__ in) { resize_w_body<4, Hc, Wc>(in, g_t2); }
__global__ void resize_h4_kernel() { resize_h_body<4, Hc, 32>(g_t2, g_l2); }

// ---------------- FiLM ----------------
__global__ void film_kernel(const float* __restrict__ cv, const float* __restrict__ cw,
                            const float* __restrict__ cb) {
    int b = blockIdx.x, j = threadIdx.x;
    float acc = cb[j];
    for (int k = 0; k < Dc; k++) acc = fmaf(cv[b * Dc + k], cw[k * 512 + j], acc);
    g_film[b * 512 + j] = acc;
}

// ---------------- weight prep: transpose + permute + hi/lo split ----------------
__global__ void prep_w0t(const float* __restrict__ w0) {
    int i = blockIdx.x * blockDim.x + threadIdx.x;
    if (i >= 256 * KPAD0) return;
    int n = i / KPAD0, kp = i % KPAD0;
    float v = 0.f;
    int orig = -1;
    if (kp < 768) orig = 42 + (kp >> 8) * 256 + (kp & 255);
    else if (kp < 810) orig = kp - 768;
    else if (kp < 813) orig = kp;
    if (orig >= 0) v = w0[orig * 256 + n];
    __nv_bfloat16 h = __float2bfloat16(v);
    g_w0t_hi[i] = h;
    g_w0t_lo[i] = __float2bfloat16(v - __bfloat162float(h));
}
__global__ void prep_hwt(const float* __restrict__ hw) {
    int i = blockIdx.x * blockDim.x + threadIdx.x;
    if (i >= 3 * 256 * 256) return;
    int L = i >> 16, r = i & 65535;
    int n = r >> 8, k = r & 255;
    float v = hw[(L * 256 + k) * 256 + n];
    __nv_bfloat16 h = __float2bfloat16(v);
    g_hwt_hi[i] = h;
    g_hwt_lo[i] = __float2bfloat16(v - __bfloat162float(h));
}

// ---------------- fused kernel ----------------
__global__ void __launch_bounds__(THREADS, 2)
fused_kernel(const float* __restrict__ grid,
             const float* __restrict__ coords,
             const float* __restrict__ oracle,
             const float* __restrict__ b0, const float* __restrict__ hb,
             const float* __restrict__ ow, const float* __restrict__ ob,
             float* __restrict__ out) {
    extern __shared__ char sm[];
    uint32_t smb = smem_u32(sm);
    float* smf = (float*)sm;
    int tid = threadIdx.x;
    int lane = tid & 31;
    int w = tid >> 5;
    int blk = blockIdx.x;
    int b = blk >> 7;               // 128 tiles of 64 per batch
    int n0 = (blk & 127) * 64;
    int mrow = (w & 1) * 32;        // warp M offset
    int ncol = (w >> 1) * 64;       // warp N offset
    int g = lane >> 2, t = lane & 3;

    // film / biases / out weights / psum init
    smf[(SM_GAMMA >> 2) + tid] = g_film[b * 512 + tid] + 1.0f;
    smf[(SM_BETA >> 2) + tid] = g_film[b * 512 + 256 + tid];
    smf[(SM_BIAS >> 2) + tid] = b0[tid];
#pragma unroll
    for (int l = 0; l < 3; l++)
        smf[(SM_BIAS >> 2) + 256 + l * 256 + tid] = hb[l * 256 + tid];
    for (int i = tid; i < 771; i += THREADS)
        smf[(SM_OW >> 2) + i] = (i < 768) ? ow[i] : ob[i - 768];
    if (tid < 192) smf[(SM_PSUM >> 2) + tid] = 0.f;

    // bilinear metadata: 3 levels x 64 samples
    if (tid < 192) {
        int lvl = tid >> 6, s = tid & 63;
        int n = n0 + s;
        int Hl = Hc >> lvl, Wl = Wc >> lvl;
        float c0 = coords[2 * n], c1 = coords[2 * n + 1];
        float y = (c0 + 1.0f) * 0.5f * (Hl - 1);
        float x = (c1 + 1.0f) * 0.5f * (Wl - 1);
        float y0f = fminf(fmaxf(floorf(y), 0.f), (float)(Hl - 1));
        float x0f = fminf(fmaxf(floorf(x), 0.f), (float)(Wl - 1));
        int y0 = (int)y0f, x0 = (int)x0f;
        int y1 = min(y0 + 1, Hl - 1), x1 = min(x0 + 1, Wl - 1);
        float wy = y - y0f, wx = x - x0f;
        int base = b * Hl * Wl;
        int* mo = (int*)(sm + SM_METAO) + tid * 4;
        float* mw = (float*)(sm + SM_METAW) + tid * 4;
        mo[0] = (base + y0 * Wl + x0) * 64;
        mo[1] = (base + y0 * Wl + x1) * 64;
        mo[2] = (base + y1 * Wl + x0) * 64;
        mo[3] = (base + y1 * Wl + x1) * 64;
        mw[0] = (1.f - wy) * (1.f - wx);
        mw[1] = (1.f - wy) * wx;
        mw[2] = wy * (1.f - wx);
        mw[3] = wy * wx;
    }
    __syncthreads();

    float acc[2][8][4];
#pragma unroll
    for (int mt = 0; mt < 2; mt++)
#pragma unroll
        for (int ns = 0; ns < 8; ns++)
#pragma unroll
            for (int i = 0; i < 4; i++) acc[mt][ns][i] = 0.f;

#define KLOOP(WH, WL_, KPAD, KW, KBASE)                                          \
    for (int kb = 0; kb < (KW); kb += 16) {                                      \
        uint32_t ah0[4], ah1[4], al0[4], al1[4];                                 \
        uint32_t arow = (uint32_t)(((mrow + (lane & 15)) * KS + kb +             \
                                    ((lane >> 4) << 3)) * 2);                    \
        ldm4(ah0, smb + A_HI + arow);                                            \
        ldm4(ah1, smb + A_HI + arow + 16 * KS * 2);                              \
        ldm4(al0, smb + A_LO + arow);                                            \
        ldm4(al1, smb + A_LO + arow + 16 * KS * 2);                              \
        int koff = (KBASE) + kb + 2 * t;                                         \
        _Pragma("unroll")                                                        \
        for (int ns = 0; ns < 8; ns++) {                                         \
            int row = ncol + ns * 8 + g;                                         \
            const __nv_bfloat16* ph = (WH) + (size_t)row * (KPAD) + koff;        \
            const __nv_bfloat16* pl = (WL_) + (size_t)row * (KPAD) + koff;       \
            uint32_t bh0 = *(const uint32_t*)ph;                                 \
            uint32_t bh1 = *(const uint32_t*)(ph + 8);                           \
            uint32_t bl0 = *(const uint32_t*)pl;                                 \
            uint32_t bl1 = *(const uint32_t*)(pl + 8);                           \
            mma16816(acc[0][ns], ah0, bh0, bh1);                                 \
            mma16816(acc[0][ns], ah0, bl0, bl1);                                 \
            mma16816(acc[0][ns], al0, bh0, bh1);                                 \
            mma16816(acc[1][ns], ah1, bh0, bh1);                                 \
            mma16816(acc[1][ns], ah1, bl0, bl1);                                 \
            mma16816(acc[1][ns], al1, bh0, bh1);                                 \
        }                                                                        \
    }

    // =================== layer 0: 4 K-chunks ===================
    for (int c = 0; c < 4; c++) {
        if (c < 3) {
            // gather level c -> A[64][256] hi/lo
            int s = tid >> 2, q = tid & 3;
            const float* lsrc = (c == 0) ? grid : (c == 1 ? g_l1 : g_l2);
            const float4* src = (const float4*)lsrc;
            const int* mo = (const int*)(sm + SM_METAO) + (c * 64 + s) * 4;
            const float* mw = (const float*)(sm + SM_METAW) + (c * 64 + s) * 4;
            int o0 = mo[0], o1 = mo[1], o2 = mo[2], o3 = mo[3];
            float w0v = mw[0], w1v = mw[1], w2v = mw[2], w3v = mw[3];
#pragma unroll
            for (int ch = 0; ch < 16; ch++) {
                int d4 = q * 16 + ch;
                float4 A = __ldg(&src[o0 + d4]);
                float4 B = __ldg(&src[o1 + d4]);
                float4 C = __ldg(&src[o2 + d4]);
                float4 D = __ldg(&src[o3 + d4]);
                float vx = w0v * A.x + w1v * B.x + w2v * C.x + w3v * D.x;
                float vy = w0v * A.y + w1v * B.y + w2v * C.y + w3v * D.y;
                float vz = w0v * A.z + w1v * B.z + w2v * C.z + w3v * D.z;
                float vw = w0v * A.w + w1v * B.w + w2v * C.w + w3v * D.w;
                int off = (s * KS + q * 64 + ch * 4) * 2;
                *(uint2*)(sm + A_HI + off) = make_uint2(pack_hi(vx, vy), pack_hi(vz, vw));
                *(uint2*)(sm + A_LO + off) = make_uint2(pack_lo(vx, vy), pack_lo(vz, vw));
            }
        } else if (tid < 64) {
            // PE + oracle + zero pad (64 k wide)
            int s = tid, n = n0 + s;
            float a[64];
            float c0v = coords[2 * n], c1v = coords[2 * n + 1];
            a[0] = c0v; a[1] = c1v;
            float pf = 3.14159265358979323846f;
#pragma unroll
            for (int f = 0; f < 10; f++) {
                float s0, q0, s1, q1;
                sincosf(c0v * pf, &s0, &q0);
                sincosf(c1v * pf, &s1, &q1);
                a[2 + 4 * f + 0] = s0; a[2 + 4 * f + 1] = s1;
                a[2 + 4 * f + 2] = q0; a[2 + 4 * f + 3] = q1;
                pf *= 2.0f;
            }
#pragma unroll
            for (int j = 0; j < 3; j++)
                a[42 + j] = oracle[((size_t)b * Nc + n) * 3 + j];
#pragma unroll
            for (int j = 45; j < 64; j++) a[j] = 0.f;
#pragma unroll
            for (int i = 0; i < 16; i++) {
                int off = (s * KS + i * 4) * 2;
                *(uint2*)(sm + A_HI + off) =
                    make_uint2(pack_hi(a[4 * i], a[4 * i + 1]), pack_hi(a[4 * i + 2], a[4 * i + 3]));
                *(uint2*)(sm + A_LO + off) =
                    make_uint2(pack_lo(a[4 * i], a[4 * i + 1]), pack_lo(a[4 * i + 2], a[4 * i + 3]));
            }
        }
        __syncthreads();
        int KW = (c < 3) ? 256 : 64;
        KLOOP(g_w0t_hi, g_w0t_lo, KPAD0, KW, c * 256)
        __syncthreads();
    }

    // =================== hidden layers ===================
    const float* gam = smf + (SM_GAMMA >> 2);
    const float* bet = smf + (SM_BETA >> 2);
    for (int L = 0; L < 3; L++) {
        const float* bias = smf + (SM_BIAS >> 2) + L * 256;
        // epilogue: gelu(FiLM) in place
#pragma unroll
        for (int mt = 0; mt < 2; mt++)
#pragma unroll
            for (int ns = 0; ns < 8; ns++) {
                int nn0 = ncol + ns * 8 + 2 * t, nn1 = nn0 + 1;
                float ga0 = gam[nn0], ga1 = gam[nn1];
                float be0 = bet[nn0], be1 = bet[nn1];
                float bi0 = bias[nn0], bi1 = bias[nn1];
                acc[mt][ns][0] = gelu_t((acc[mt][ns][0] + bi0) * ga0 + be0);
                acc[mt][ns][1] = gelu_t((acc[mt][ns][1] + bi1) * ga1 + be1);
                acc[mt][ns][2] = gelu_t((acc[mt][ns][2] + bi0) * ga0 + be0);
                acc[mt][ns][3] = gelu_t((acc[mt][ns][3] + bi1) * ga1 + be1);
            }
        __syncthreads();
#pragma unroll
        for (int mt = 0; mt < 2; mt++)
#pragma unroll
            for (int ns = 0; ns < 8; ns++) {
                int nn0 = ncol + ns * 8 + 2 * t;
                int r0 = mrow + mt * 16 + g, r1 = r0 + 8;
                *(uint32_t*)(sm + A_HI + (r0 * KS + nn0) * 2) = pack_hi(acc[mt][ns][0], acc[mt][ns][1]);
                *(uint32_t*)(sm + A_LO + (r0 * KS + nn0) * 2) = pack_lo(acc[mt][ns][0], acc[mt][ns][1]);
                *(uint32_t*)(sm + A_HI + (r1 * KS + nn0) * 2) = pack_hi(acc[mt][ns][2], acc[mt][ns][3]);
                *(uint32_t*)(sm + A_LO + (r1 * KS + nn0) * 2) = pack_lo(acc[mt][ns][2], acc[mt][ns][3]);
#pragma unroll
                for (int i = 0; i < 4; i++) acc[mt][ns][i] = 0.f;
            }
        __syncthreads();
        KLOOP(g_hwt_hi + (size_t)L * 65536, g_hwt_lo + (size_t)L * 65536, 256, 256, 0)
    }

    // =================== output layer ===================
    {
        const float* bias = smf + (SM_BIAS >> 2) + 3 * 256;
        const float* oww = smf + (SM_OW >> 2);
        float p[4][3];
#pragma unroll
        for (int i = 0; i < 4; i++) p[i][0] = p[i][1] = p[i][2] = 0.f;
#pragma unroll
        for (int mt = 0; mt < 2; mt++)
#pragma unroll
            for (int ns = 0; ns < 8; ns++) {
                int nn0 = ncol + ns * 8 + 2 * t, nn1 = nn0 + 1;
                float ga0 = gam[nn0], ga1 = gam[nn1];
                float be0 = bet[nn0], be1 = bet[nn1];
                float bi0 = bias[nn0], bi1 = bias[nn1];
                float v0 = gelu_t((acc[mt][ns][0] + bi0) * ga0 + be0);
                float v1 = gelu_t((acc[mt][ns][1] + bi1) * ga1 + be1);
                float v2 = gelu_t((acc[mt][ns][2] + bi0) * ga0 + be0);
                float v3 = gelu_t((acc[mt][ns][3] + bi1) * ga1 + be1);
#pragma unroll
                for (int o = 0; o < 3; o++) {
                    float w0o = oww[nn0 * 3 + o], w1o = oww[nn1 * 3 + o];
                    p[mt * 2 + 0][o] += v0 * w0o + v1 * w1o;
                    p[mt * 2 + 1][o] += v2 * w0o + v3 * w1o;
                }
            }
        // reduce across t (lanes xor 1, 2)
#pragma unroll
        for (int i = 0; i < 4; i++)
#pragma unroll
            for (int o = 0; o < 3; o++) {
                p[i][o] += __shfl_xor_sync(0xffffffffu, p[i][o], 1);
                p[i][o] += __shfl_xor_sync(0xffffffffu, p[i][o], 2);
            }
        if (t == 0) {
#pragma unroll
            for (int mt = 0; mt < 2; mt++) {
                int r0 = mrow + mt * 16 + g, r1 = r0 + 8;
#pragma unroll
                for (int o = 0; o < 3; o++) {
                    atomicAdd(smf + (SM_PSUM >> 2) + r0 * 3 + o, p[mt * 2 + 0][o]);
                    atomicAdd(smf + (SM_PSUM >> 2) + r1 * 3 + o, p[mt * 2 + 1][o]);
                }
            }
        }
    }
    __syncthreads();
    if (tid < 64) {
        const float* obv = smf + (SM_OW >> 2) + 768;
#pragma unroll
        for (int o = 0; o < 3; o++)
            out[((size_t)b * Nc + n0 + tid) * 3 + o] =
                tanhf(smf[(SM_PSUM >> 2) + tid * 3 + o] + obv[o]);
    }
}

// ---------------- launch ----------------
extern "C" void kernel_launch(void* const* d_in, const int* in_sizes, int n_in,
                              void* d_out, int out_size) {
    const float* grid   = (const float*)d_in[0];
    const float* cv     = (const float*)d_in[1];
    const float* coords = (const float*)d_in[2];
    const float* oracle = (const float*)d_in[3];
    const float* w0     = (const float*)d_in[4];
    const float* b0     = (const float*)d_in[5];
    const float* hw     = (const float*)d_in[6];
    const float* hb     = (const float*)d_in[7];
    const float* cw     = (const float*)d_in[8];
    const float* cb     = (const float*)d_in[9];
    const float* ow     = (const float*)d_in[10];
    const float* ob     = (const float*)d_in[11];
    float* out = (float*)d_out;

    cudaFuncSetAttribute(fused_kernel, cudaFuncAttributeMaxDynamicSharedMemorySize, SM_TOTAL);

    resize_w2_kernel<<<(Bc * Hc * 64 * 64 + 255) / 256, 256>>>(grid);
    resize_h2_kernel<<<(Bc * 64 * 64 * 64 + 255) / 256, 256>>>();
    resize_w4_kernel<<<(Bc * Hc * 32 * 64 + 255) / 256, 256>>>(grid);
    resize_h4_kernel<<<(Bc * 32 * 32 * 64 + 255) / 256, 256>>>();
    film_kernel<<<Bc, 512>>>(cv, cw, cb);
    prep_w0t<<<(256 * KPAD0 + 255) / 256, 256>>>(w0);
    prep_hwt<<<(3 * 256 * 256 + 255) / 256, 256>>>(hw);
    fused_kernel<<<Bc * Nc / 64, THREADS, SM_TOTAL>>>(grid, coords, oracle,
                                                      b0, hb, ow, ob, out);
}

// round 7
// speedup vs baseline: 2.5679x; 1.6638x over previous
#include <cuda_runtime.h>
#include <cuda_bf16.h>
#include <math.h>
#include <stdint.h>

#define Bc    8
#define Hc    128
#define Wc    128
#define Dc    256
#define Nc    8192
#define THREADS 256

// SMEM byte offsets
#define KS       264            // bf16 stride per activation row (528B = 33*16B)
#define A_HI     0              // 64*264*2 = 33792
#define A_LO     33792
#define SM_METAO 67584          // 3*64*4 int
#define SM_METAW 70656          // 3*64*4 float
#define SM_GAMMA 73728          // 256 f32
#define SM_BETA  74752
#define SM_BIAS  75776          // 4*256 f32
#define SM_OW    79872          // 771 f32
#define SM_PSUM  82960          // 64*3 f32
#define SM_TOTAL 83776

// ---------------- device scratch ----------------
__device__ float g_t1[Bc * Hc * 64 * Dc];
__device__ float g_l1[Bc * 64 * 64 * Dc];
__device__ float g_t2[Bc * Hc * 32 * Dc];
__device__ float g_l2[Bc * 32 * 32 * Dc];
__device__ float g_film[Bc * 512];
// fragment-packed weights: [kb][n8 group][lane] -> {bh0, bh1, bl0, bl1}
__device__ __align__(16) uint4 g_w0f[52 * 32 * 32];      // layer0, K padded to 832
__device__ __align__(16) uint4 g_hwf[3 * 16 * 32 * 32];  // hidden layers

// ---------------- helpers ----------------
__device__ __forceinline__ uint32_t smem_u32(const void* p) {
    uint32_t a;
    asm("{ .reg .u64 t; cvta.to.shared.u64 t, %1; cvt.u32.u64 %0, t; }" : "=r"(a) : "l"(p));
    return a;
}
__device__ __forceinline__ void ldm4(uint32_t* r, uint32_t addr) {
    asm volatile("ldmatrix.sync.aligned.m8n8.x4.shared.b16 {%0,%1,%2,%3}, [%4];"
        : "=r"(r[0]), "=r"(r[1]), "=r"(r[2]), "=r"(r[3]) : "r"(addr));
}
__device__ __forceinline__ void mma16816(float* c, const uint32_t* a, uint32_t b0, uint32_t b1) {
    asm volatile("mma.sync.aligned.m16n8k16.row.col.f32.bf16.bf16.f32 "
        "{%0,%1,%2,%3}, {%4,%5,%6,%7}, {%8,%9}, {%0,%1,%2,%3};"
        : "+f"(c[0]), "+f"(c[1]), "+f"(c[2]), "+f"(c[3])
        : "r"(a[0]), "r"(a[1]), "r"(a[2]), "r"(a[3]), "r"(b0), "r"(b1));
}
__device__ __forceinline__ uint32_t pack_hi(float x, float y) {
    __nv_bfloat162 v(__float2bfloat16(x), __float2bfloat16(y));
    return *(uint32_t*)&v;
}
__device__ __forceinline__ uint32_t pack_lo(float x, float y) {
    float hx = __bfloat162float(__float2bfloat16(x));
    float hy = __bfloat162float(__float2bfloat16(y));
    __nv_bfloat162 v(__float2bfloat16(x - hx), __float2bfloat16(y - hy));
    return *(uint32_t*)&v;
}
__device__ __forceinline__ float gelu_t(float x) {
    float x3 = x * x * x;
    float t = tanhf(0.7978845608028654f * (x + 0.044715f * x3));
    return 0.5f * x * (1.0f + t);
}

// ---------------- resize (antialiased triangle, separable) ----------------
template <int INV, int HL, int WIN>
__device__ __forceinline__ void resize_w_body(const float* __restrict__ in, float* __restrict__ out) {
    const int WOUT = WIN / INV, NT = 2 * INV;
    int idx = blockIdx.x * blockDim.x + threadIdx.x;
    if (idx >= Bc * HL * WOUT * 64) return;
    int d4 = idx & 63, t = idx >> 6;
    int xo = t % WOUT; t /= WOUT;
    int y = t % HL, b = t / HL;
    float sf = (xo + 0.5f) * INV - 0.5f;
    int j0 = INV * xo - (INV / 2);
    float w[NT], wsum = 0.f;
#pragma unroll
    for (int i = 0; i < NT; i++) {
        int j = j0 + i;
        float ww = 1.0f - fabsf((float)j - sf) * (1.0f / INV);
        ww = (j >= 0 && j < WIN) ? fmaxf(ww, 0.f) : 0.f;
        w[i] = ww; wsum += ww;
    }
    float inv = 1.0f / wsum;
    const float4* ip = (const float4*)in + ((size_t)(b * HL + y) * WIN) * 64 + d4;
    float4 acc = make_float4(0.f, 0.f, 0.f, 0.f);
#pragma unroll
    for (int i = 0; i < NT; i++)
        if (w[i] > 0.f) {
            float4 v = __ldg(&ip[(j0 + i) * 64]);
            float ww = w[i] * inv;
            acc.x += ww * v.x; acc.y += ww * v.y; acc.z += ww * v.z; acc.w += ww * v.w;
        }
    ((float4*)out)[((size_t)(b * HL + y) * WOUT + xo) * 64 + d4] = acc;
}
template <int INV, int HIN, int WL>
__device__ __forceinline__ void resize_h_body(const float* __restrict__ in, float* __restrict__ out) {
    const int HOUT = HIN / INV, NT = 2 * INV;
    int idx = blockIdx.x * blockDim.x + threadIdx.x;
    if (idx >= Bc * HOUT * WL * 64) return;
    int d4 = idx & 63, t = idx >> 6;
    int x = t % WL; t /= WL;
    int yo = t % HOUT, b = t / HOUT;
    float sf = (yo + 0.5f) * INV - 0.5f;
    int j0 = INV * yo - (INV / 2);
    float w[NT], wsum = 0.f;
#pragma unroll
    for (int i = 0; i < NT; i++) {
        int j = j0 + i;
        float ww = 1.0f - fabsf((float)j - sf) * (1.0f / INV);
        ww = (j >= 0 && j < HIN) ? fmaxf(ww, 0.f) : 0.f;
        w[i] = ww; wsum += ww;
    }
    float inv = 1.0f / wsum;
    const float4* ip = (const float4*)in + ((size_t)b * HIN * WL + x) * 64 + d4;
    float4 acc = make_float4(0.f, 0.f, 0.f, 0.f);
#pragma unroll
    for (int i = 0; i < NT; i++)
        if (w[i] > 0.f) {
            float4 v = __ldg(&ip[(size_t)(j0 + i) * WL * 64]);
            float ww = w[i] * inv;
            acc.x += ww * v.x; acc.y += ww * v.y; acc.z += ww * v.z; acc.w += ww * v.w;
        }
    ((float4*)out)[((size_t)(b * HOUT + yo) * WL + x) * 64 + d4] = acc;
}
__global__ void resize_w2_kernel(const float* __restrict__ in) { resize_w_body<2, Hc, Wc>(in, g_t1); }
__global__ void resize_h2_kernel() { resize_h_body<2, Hc, 64>(g_t1, g_l1); }
__global__ void resize_w4_kernel(const float* __restrict__ in) { resize_w_body<4, Hc, Wc>(in, g_t2); }
__global__ void resize_h4_kernel() { resize_h_body<4, Hc, 32>(g_t2, g_l2); }

// ---------------- FiLM ----------------
__global__ void film_kernel(const float* __restrict__ cv, const float* __restrict__ cw,
                            const float* __restrict__ cb) {
    int b = blockIdx.x, j = threadIdx.x;
    float acc = cb[j];
    for (int k = 0; k < Dc; k++) acc = fmaf(cv[b * Dc + k], cw[k * 512 + j], acc);
    g_film[b * 512 + j] = acc;
}

// ---------------- weight prep: fragment packing + hi/lo split ----------------
__device__ __forceinline__ float w0val(const float* __restrict__ w0, int kp, int n) {
    if (kp >= 813) return 0.f;
    int orig;
    if (kp < 768) orig = 42 + (kp >> 8) * 256 + (kp & 255);
    else if (kp < 810) orig = kp - 768;
    else orig = kp;
    return w0[orig * 256 + n];
}

__global__ void prep_w0f(const float* __restrict__ w0) {
    int idx = blockIdx.x * blockDim.x + threadIdx.x;
    if (idx >= 52 * 32 * 32) return;
    int lane = idx & 31, nq = (idx >> 5) & 31, kb = idx >> 10;
    int g = lane >> 2, t = lane & 3;
    int row = nq * 8 + g;
    int k0 = kb * 16 + 2 * t;
    float v0 = w0val(w0, k0, row),     v1 = w0val(w0, k0 + 1, row);
    float v2 = w0val(w0, k0 + 8, row), v3 = w0val(w0, k0 + 9, row);
    g_w0f[idx] = make_uint4(pack_hi(v0, v1), pack_hi(v2, v3),
                            pack_lo(v0, v1), pack_lo(v2, v3));
}
__global__ void prep_hwf(const float* __restrict__ hw) {
    int idx = blockIdx.x * blockDim.x + threadIdx.x;
    if (idx >= 3 * 16 * 32 * 32) return;
    int lane = idx & 31, nq = (idx >> 5) & 31, kb = (idx >> 10) & 15, L = idx >> 14;
    int g = lane >> 2, t = lane & 3;
    int row = nq * 8 + g;
    int k0 = kb * 16 + 2 * t;
    const float* W = hw + (size_t)L * 65536;
    float v0 = W[k0 * 256 + row],       v1 = W[(k0 + 1) * 256 + row];
    float v2 = W[(k0 + 8) * 256 + row], v3 = W[(k0 + 9) * 256 + row];
    g_hwf[idx] = make_uint4(pack_hi(v0, v1), pack_hi(v2, v3),
                            pack_lo(v0, v1), pack_lo(v2, v3));
}

// ---------------- fused kernel ----------------
__global__ void __launch_bounds__(THREADS, 2)
fused_kernel(const float* __restrict__ grid,
             const float* __restrict__ coords,
             const float* __restrict__ oracle,
             const float* __restrict__ b0, const float* __restrict__ hb,
             const float* __restrict__ ow, const float* __restrict__ ob,
             float* __restrict__ out) {
    extern __shared__ char sm[];
    uint32_t smb = smem_u32(sm);
    float* smf = (float*)sm;
    int tid = threadIdx.x;
    int lane = tid & 31;
    int w = tid >> 5;
    int blk = blockIdx.x;
    int b = blk >> 7;               // 128 tiles of 64 per batch
    int n0 = (blk & 127) * 64;
    int mrow = (w & 1) * 32;        // warp M offset
    int ncol = (w >> 1) * 64;       // warp N offset
    int g = lane >> 2, t = lane & 3;

    // film / biases / out weights / psum init
    smf[(SM_GAMMA >> 2) + tid] = g_film[b * 512 + tid] + 1.0f;
    smf[(SM_BETA >> 2) + tid] = g_film[b * 512 + 256 + tid];
    smf[(SM_BIAS >> 2) + tid] = b0[tid];
#pragma unroll
    for (int l = 0; l < 3; l++)
        smf[(SM_BIAS >> 2) + 256 + l * 256 + tid] = hb[l * 256 + tid];
    for (int i = tid; i < 771; i += THREADS)
        smf[(SM_OW >> 2) + i] = (i < 768) ? ow[i] : ob[i - 768];
    if (tid < 192) smf[(SM_PSUM >> 2) + tid] = 0.f;

    // bilinear metadata: 3 levels x 64 samples
    if (tid < 192) {
        int lvl = tid >> 6, s = tid & 63;
        int n = n0 + s;
        int Hl = Hc >> lvl, Wl = Wc >> lvl;
        float c0 = coords[2 * n], c1 = coords[2 * n + 1];
        float y = (c0 + 1.0f) * 0.5f * (Hl - 1);
        float x = (c1 + 1.0f) * 0.5f * (Wl - 1);
        float y0f = fminf(fmaxf(floorf(y), 0.f), (float)(Hl - 1));
        float x0f = fminf(fmaxf(floorf(x), 0.f), (float)(Wl - 1));
        int y0 = (int)y0f, x0 = (int)x0f;
        int y1 = min(y0 + 1, Hl - 1), x1 = min(x0 + 1, Wl - 1);
        float wy = y - y0f, wx = x - x0f;
        int base = b * Hl * Wl;
        int* mo = (int*)(sm + SM_METAO) + tid * 4;
        float* mw = (float*)(sm + SM_METAW) + tid * 4;
        mo[0] = (base + y0 * Wl + x0) * 64;
        mo[1] = (base + y0 * Wl + x1) * 64;
        mo[2] = (base + y1 * Wl + x0) * 64;
        mo[3] = (base + y1 * Wl + x1) * 64;
        mw[0] = (1.f - wy) * (1.f - wx);
        mw[1] = (1.f - wy) * wx;
        mw[2] = wy * (1.f - wx);
        mw[3] = wy * wx;
    }
    __syncthreads();

    float acc[2][8][4];
#pragma unroll
    for (int mt = 0; mt < 2; mt++)
#pragma unroll
        for (int ns = 0; ns < 8; ns++)
#pragma unroll
            for (int i = 0; i < 4; i++) acc[mt][ns][i] = 0.f;

// fragment-packed KLOOP: per 16-K block: 4 ldmatrix + 8 coalesced LDG.128 + 48 HMMA
#define KLOOP(FRAG, NKB, KB0)                                                    \
    _Pragma("unroll 2")                                                          \
    for (int kbi = 0; kbi < (NKB); kbi++) {                                      \
        uint32_t ah0[4], ah1[4], al0[4], al1[4];                                 \
        uint32_t arow = (uint32_t)(((mrow + (lane & 15)) * KS + kbi * 16 +       \
                                    ((lane >> 4) << 3)) * 2);                    \
        ldm4(ah0, smb + A_HI + arow);                                            \
        ldm4(ah1, smb + A_HI + arow + 16 * KS * 2);                              \
        ldm4(al0, smb + A_LO + arow);                                            \
        ldm4(al1, smb + A_LO + arow + 16 * KS * 2);                              \
        const uint4* wf = (FRAG) + ((size_t)((KB0) + kbi) * 32 + (ncol >> 3)) * 32 + lane; \
        _Pragma("unroll")                                                        \
        for (int ns = 0; ns < 8; ns++) {                                         \
            uint4 f = __ldg(wf + ns * 32);                                       \
            mma16816(acc[0][ns], ah0, f.x, f.y);                                 \
            mma16816(acc[0][ns], ah0, f.z, f.w);                                 \
            mma16816(acc[0][ns], al0, f.x, f.y);                                 \
            mma16816(acc[1][ns], ah1, f.x, f.y);                                 \
            mma16816(acc[1][ns], ah1, f.z, f.w);                                 \
            mma16816(acc[1][ns], al1, f.x, f.y);                                 \
        }                                                                        \
    }

    // =================== layer 0: 4 K-chunks ===================
    for (int c = 0; c < 4; c++) {
        if (c < 3) {
            // gather level c -> A[64][256] hi/lo
            int s = tid >> 2, q = tid & 3;
            const float* lsrc = (c == 0) ? grid : (c == 1 ? g_l1 : g_l2);
            const float4* src = (const float4*)lsrc;
            const int* mo = (const int*)(sm + SM_METAO) + (c * 64 + s) * 4;
            const float* mw = (const float*)(sm + SM_METAW) + (c * 64 + s) * 4;
            int o0 = mo[0], o1 = mo[1], o2 = mo[2], o3 = mo[3];
            float w0v = mw[0], w1v = mw[1], w2v = mw[2], w3v = mw[3];
#pragma unroll
            for (int ch = 0; ch < 16; ch++) {
                int d4 = q * 16 + ch;
                float4 A = __ldg(&src[o0 + d4]);
                float4 B = __ldg(&src[o1 + d4]);
                float4 C = __ldg(&src[o2 + d4]);
                float4 D = __ldg(&src[o3 + d4]);
                float vx = w0v * A.x + w1v * B.x + w2v * C.x + w3v * D.x;
                float vy = w0v * A.y + w1v * B.y + w2v * C.y + w3v * D.y;
                float vz = w0v * A.z + w1v * B.z + w2v * C.z + w3v * D.z;
                float vw = w0v * A.w + w1v * B.w + w2v * C.w + w3v * D.w;
                int off = (s * KS + q * 64 + ch * 4) * 2;
                *(uint2*)(sm + A_HI + off) = make_uint2(pack_hi(vx, vy), pack_hi(vz, vw));
                *(uint2*)(sm + A_LO + off) = make_uint2(pack_lo(vx, vy), pack_lo(vz, vw));
            }
        } else if (tid < 64) {
            // PE + oracle + zero pad (64 k wide)
            int s = tid, n = n0 + s;
            float a[64];
            float c0v = coords[2 * n], c1v = coords[2 * n + 1];
            a[0] = c0v; a[1] = c1v;
            float pf = 3.14159265358979323846f;
#pragma unroll
            for (int f = 0; f < 10; f++) {
                float s0, q0, s1, q1;
                sincosf(c0v * pf, &s0, &q0);
                sincosf(c1v * pf, &s1, &q1);
                a[2 + 4 * f + 0] = s0; a[2 + 4 * f + 1] = s1;
                a[2 + 4 * f + 2] = q0; a[2 + 4 * f + 3] = q1;
                pf *= 2.0f;
            }
#pragma unroll
            for (int j = 0; j < 3; j++)
                a[42 + j] = oracle[((size_t)b * Nc + n) * 3 + j];
#pragma unroll
            for (int j = 45; j < 64; j++) a[j] = 0.f;
#pragma unroll
            for (int i = 0; i < 16; i++) {
                int off = (s * KS + i * 4) * 2;
                *(uint2*)(sm + A_HI + off) =
                    make_uint2(pack_hi(a[4 * i], a[4 * i + 1]), pack_hi(a[4 * i + 2], a[4 * i + 3]));
                *(uint2*)(sm + A_LO + off) =
                    make_uint2(pack_lo(a[4 * i], a[4 * i + 1]), pack_lo(a[4 * i + 2], a[4 * i + 3]));
            }
        }
        __syncthreads();
        if (c < 3) { KLOOP(g_w0f, 16, c * 16) }
        else       { KLOOP(g_w0f, 4, 48) }
        __syncthreads();
    }

    // =================== hidden layers ===================
    const float* gam = smf + (SM_GAMMA >> 2);
    const float* bet = smf + (SM_BETA >> 2);
    for (int L = 0; L < 3; L++) {
        const float* bias = smf + (SM_BIAS >> 2) + L * 256;
        // epilogue: gelu(FiLM) in place
#pragma unroll
        for (int mt = 0; mt < 2; mt++)
#pragma unroll
            for (int ns = 0; ns < 8; ns++) {
                int nn0 = ncol + ns * 8 + 2 * t, nn1 = nn0 + 1;
                float ga0 = gam[nn0], ga1 = gam[nn1];
                float be0 = bet[nn0], be1 = bet[nn1];
                float bi0 = bias[nn0], bi1 = bias[nn1];
                acc[mt][ns][0] = gelu_t((acc[mt][ns][0] + bi0) * ga0 + be0);
                acc[mt][ns][1] = gelu_t((acc[mt][ns][1] + bi1) * ga1 + be1);
                acc[mt][ns][2] = gelu_t((acc[mt][ns][2] + bi0) * ga0 + be0);
                acc[mt][ns][3] = gelu_t((acc[mt][ns][3] + bi1) * ga1 + be1);
            }
        __syncthreads();
#pragma unroll
        for (int mt = 0; mt < 2; mt++)
#pragma unroll
            for (int ns = 0; ns < 8; ns++) {
                int nn0 = ncol + ns * 8 + 2 * t;
                int r0 = mrow + mt * 16 + g, r1 = r0 + 8;
                *(uint32_t*)(sm + A_HI + (r0 * KS + nn0) * 2) = pack_hi(acc[mt][ns][0], acc[mt][ns][1]);
                *(uint32_t*)(sm + A_LO + (r0 * KS + nn0) * 2) = pack_lo(acc[mt][ns][0], acc[mt][ns][1]);
                *(uint32_t*)(sm + A_HI + (r1 * KS + nn0) * 2) = pack_hi(acc[mt][ns][2], acc[mt][ns][3]);
                *(uint32_t*)(sm + A_LO + (r1 * KS + nn0) * 2) = pack_lo(acc[mt][ns][2], acc[mt][ns][3]);
#pragma unroll
                for (int i = 0; i < 4; i++) acc[mt][ns][i] = 0.f;
            }
        __syncthreads();
        KLOOP(g_hwf + (size_t)L * 16384, 16, 0)
    }

    // =================== output layer ===================
    {
        const float* bias = smf + (SM_BIAS >> 2) + 3 * 256;
        const float* oww = smf + (SM_OW >> 2);
        float p[4][3];
#pragma unroll
        for (int i = 0; i < 4; i++) p[i][0] = p[i][1] = p[i][2] = 0.f;
#pragma unroll
        for (int mt = 0; mt < 2; mt++)
#pragma unroll
            for (int ns = 0; ns < 8; ns++) {
                int nn0 = ncol + ns * 8 + 2 * t, nn1 = nn0 + 1;
                float ga0 = gam[nn0], ga1 = gam[nn1];
                float be0 = bet[nn0], be1 = bet[nn1];
                float bi0 = bias[nn0], bi1 = bias[nn1];
                float v0 = gelu_t((acc[mt][ns][0] + bi0) * ga0 + be0);
                float v1 = gelu_t((acc[mt][ns][1] + bi1) * ga1 + be1);
                float v2 = gelu_t((acc[mt][ns][2] + bi0) * ga0 + be0);
                float v3 = gelu_t((acc[mt][ns][3] + bi1) * ga1 + be1);
#pragma unroll
                for (int o = 0; o < 3; o++) {
                    float w0o = oww[nn0 * 3 + o], w1o = oww[nn1 * 3 + o];
                    p[mt * 2 + 0][o] += v0 * w0o + v1 * w1o;
                    p[mt * 2 + 1][o] += v2 * w0o + v3 * w1o;
                }
            }
#pragma unroll
        for (int i = 0; i < 4; i++)
#pragma unroll
            for (int o = 0; o < 3; o++) {
                p[i][o] += __shfl_xor_sync(0xffffffffu, p[i][o], 1);
                p[i][o] += __shfl_xor_sync(0xffffffffu, p[i][o], 2);
            }
        if (t == 0) {
#pragma unroll
            for (int mt = 0; mt < 2; mt++) {
                int r0 = mrow + mt * 16 + g, r1 = r0 + 8;
#pragma unroll
                for (int o = 0; o < 3; o++) {
                    atomicAdd(smf + (SM_PSUM >> 2) + r0 * 3 + o, p[mt * 2 + 0][o]);
                    atomicAdd(smf + (SM_PSUM >> 2) + r1 * 3 + o, p[mt * 2 + 1][o]);
                }
            }
        }
    }
    __syncthreads();
    if (tid < 64) {
        const float* obv = smf + (SM_OW >> 2) + 768;
#pragma unroll
        for (int o = 0; o < 3; o++)
            out[((size_t)b * Nc + n0 + tid) * 3 + o] =
                tanhf(smf[(SM_PSUM >> 2) + tid * 3 + o] + obv[o]);
    }
}

// ---------------- launch ----------------
extern "C" void kernel_launch(void* const* d_in, const int* in_sizes, int n_in,
                              void* d_out, int out_size) {
    const float* grid   = (const float*)d_in[0];
    const float* cv     = (const float*)d_in[1];
    const float* coords = (const float*)d_in[2];
    const float* oracle = (const float*)d_in[3];
    const float* w0     = (const float*)d_in[4];
    const float* b0     = (const float*)d_in[5];
    const float* hw     = (const float*)d_in[6];
    const float* hb     = (const float*)d_in[7];
    const float* cw     = (const float*)d_in[8];
    const float* cb     = (const float*)d_in[9];
    const float* ow     = (const float*)d_in[10];
    const float* ob     = (const float*)d_in[11];
    float* out = (float*)d_out;

    cudaFuncSetAttribute(fused_kernel, cudaFuncAttributeMaxDynamicSharedMemorySize, SM_TOTAL);

    resize_w2_kernel<<<(Bc * Hc * 64 * 64 + 255) / 256, 256>>>(grid);
    resize_h2_kernel<<<(Bc * 64 * 64 * 64 + 255) / 256, 256>>>();
    resize_w4_kernel<<<(Bc * Hc * 32 * 64 + 255) / 256, 256>>>(grid);
    resize_h4_kernel<<<(Bc * 32 * 32 * 64 + 255) / 256, 256>>>();
    film_kernel<<<Bc, 512>>>(cv, cw, cb);
    prep_w0f<<<(52 * 32 * 32 + 255) / 256, 256>>>(w0);
    prep_hwf<<<(3 * 16 * 32 * 32 + 255) / 256, 256>>>(hw);
    fused_kernel<<<Bc * Nc / 64, THREADS, SM_TOTAL>>>(grid, coords, oracle,
                                                      b0, hb, ow, ob, out);
}